// round 3
// baseline (speedup 1.0000x reference)
#include <cuda_runtime.h>
#include <cuda_bf16.h>
#include <cstdint>
#include <cstdio>

// Problem constants
#define BB 2
#define TT 2048
#define QDIM 512
#define HH 8
#define DHH 64
#define WW 64
#define DM 512          // H*DH
#define NTOK (BB*TT)    // 4096

// Scratch (static device globals; no allocs allowed)
__device__ float g_q[NTOK * DM];        // roped q projection
__device__ float g_kv[NTOK * 2 * DM];   // [rope(k_p) | v_p] per token (the "concat")
__device__ float g_ctx[NTOK * DM];      // attention output before Wlin

// ---------------------------------------------------------------------------
// SGEMM: C[M,N] = A[M,K] * Bw[N,K]^T (+bias). Both A and Bw are K-major.
// Block tile 128x64, BK=16, 256 threads, 8x4 micro-tile per thread.
// One-stage software pipeline: next tile's global loads issued before the
// current tile's FMA loop.
// ---------------------------------------------------------------------------
#define BM 128
#define BN 64
#define BK 16

__global__ __launch_bounds__(256) void sgemm_kernel(
    const float* __restrict__ A, const float* __restrict__ Bw,
    float* __restrict__ C, int M, int N, int K,
    const float* __restrict__ bias)
{
    __shared__ float As[BK][BM + 4];
    __shared__ float Bs[BK][BN];

    const int tid = threadIdx.x;
    const int m0 = blockIdx.y * BM;
    const int n0 = blockIdx.x * BN;
    const int tx = tid & 15;   // column group (x4)
    const int ty = tid >> 4;   // row group (x8)

    const int aRow = tid >> 2;        // 0..63 (two rows: +0, +64)
    const int aCol = (tid & 3) * 4;   // 0,4,8,12
    const int bRow = tid >> 2;        // 0..63
    const int bCol = (tid & 3) * 4;

    const float* aPtr0 = &A[(size_t)(m0 + aRow) * K + aCol];
    const float* aPtr1 = &A[(size_t)(m0 + aRow + 64) * K + aCol];
    const float* bPtr  = &Bw[(size_t)(n0 + bRow) * K + bCol];

    float acc[8][4];
#pragma unroll
    for (int i = 0; i < 8; i++)
#pragma unroll
        for (int j = 0; j < 4; j++) acc[i][j] = 0.f;

    // prologue: load first k-tile
    float4 va0 = *(const float4*)(aPtr0);
    float4 va1 = *(const float4*)(aPtr1);
    float4 vb  = *(const float4*)(bPtr);

    for (int k0 = 0; k0 < K; k0 += BK) {
        // commit staged registers to smem
        As[aCol + 0][aRow]      = va0.x;
        As[aCol + 1][aRow]      = va0.y;
        As[aCol + 2][aRow]      = va0.z;
        As[aCol + 3][aRow]      = va0.w;
        As[aCol + 0][aRow + 64] = va1.x;
        As[aCol + 1][aRow + 64] = va1.y;
        As[aCol + 2][aRow + 64] = va1.z;
        As[aCol + 3][aRow + 64] = va1.w;
        Bs[bCol + 0][bRow] = vb.x;
        Bs[bCol + 1][bRow] = vb.y;
        Bs[bCol + 2][bRow] = vb.z;
        Bs[bCol + 3][bRow] = vb.w;
        __syncthreads();

        // prefetch next tile (overlaps with FMA loop below)
        const int kn = k0 + BK;
        if (kn < K) {
            va0 = *(const float4*)(aPtr0 + kn);
            va1 = *(const float4*)(aPtr1 + kn);
            vb  = *(const float4*)(bPtr + kn);
        }

#pragma unroll
        for (int kk = 0; kk < BK; kk++) {
            float a[8], b[4];
#pragma unroll
            for (int i = 0; i < 8; i++) a[i] = As[kk][ty * 8 + i];
#pragma unroll
            for (int j = 0; j < 4; j++) b[j] = Bs[kk][tx * 4 + j];
#pragma unroll
            for (int i = 0; i < 8; i++)
#pragma unroll
                for (int j = 0; j < 4; j++)
                    acc[i][j] = fmaf(a[i], b[j], acc[i][j]);
        }
        __syncthreads();
    }

#pragma unroll
    for (int i = 0; i < 8; i++) {
        const int m = m0 + ty * 8 + i;
#pragma unroll
        for (int j = 0; j < 4; j++) {
            const int n = n0 + tx * 4 + j;
            float v = acc[i][j];
            if (bias) v += bias[n];
            C[(size_t)m * N + n] = v;
        }
    }
}

// ---------------------------------------------------------------------------
// RoPE over the full 512-dim projection: pairs (i, i+256), i in [0,256).
// Applied in-place to g_q (512 wide) and to the first 512 cols of g_kv.
// ---------------------------------------------------------------------------
__global__ void rope_kernel(float* __restrict__ q, float* __restrict__ kv)
{
    const int row = blockIdx.x;       // 0..NTOK-1
    const int i = threadIdx.x;        // 0..255
    const int t = row & (TT - 1);     // position within sequence

    const float inv = powf(100.0f, -(float)i * (1.0f / 256.0f));
    const float ang = (float)t * inv;
    float s, c;
    sincosf(ang, &s, &c);

    float* qr = q + (size_t)row * DM;
    float x1 = qr[i], x2 = qr[i + 256];
    qr[i]       = x1 * c - x2 * s;
    qr[i + 256] = x2 * c + x1 * s;

    float* kr = kv + (size_t)row * (2 * DM);
    x1 = kr[i]; x2 = kr[i + 256];
    kr[i]       = x1 * c - x2 * s;
    kr[i + 256] = x2 * c + x1 * s;
}

// ---------------------------------------------------------------------------
// Sliding-window sigmoid attention.
// NOTE the reference's reshape quirk: head h's K = concat[128h : 128h+64],
// head h's V = concat[128h+64 : 128h+128], where concat = [rope(k_p), v_p].
// Block: one (b, h, 64-query tile). 256 threads.
// ---------------------------------------------------------------------------
#define QTILE 64
#define KTILE 128   // covers query tile window span: t0-63 .. t0+63 (+1 spare)
#define KS_LD 68    // padded row stride (16B-aligned rows, conflict-spread)

__global__ __launch_bounds__(256) void attn_kernel(
    const float* __restrict__ q, const float* __restrict__ kv,
    const int* __restrict__ mask, float* __restrict__ ctx)
{
    const int t0 = blockIdx.x * QTILE;
    const int h  = blockIdx.y;
    const int b  = blockIdx.z;

    extern __shared__ float sm[];
    float* qs = sm;                         // 64 x 64
    float* ks = qs + QTILE * DHH;           // 128 x 68 (padded, 16B-aligned rows)
    float* vs = ks + KTILE * KS_LD;         // 128 x 64
    float* ss = vs + KTILE * DHH;           // 64 x 64

    const int tid = threadIdx.x;

    const float* qbase = q + ((size_t)b * TT) * DM + h * DHH;
    const float* kbase = kv + ((size_t)b * TT) * (2 * DM) + h * 128;       // concat[128h..]
    const float* vbase = kbase + 64;                                       // concat[128h+64..]

    // load Q tile (vectorized: 64 rows x 16 float4)
    for (int idx = tid; idx < QTILE * (DHH / 4); idx += 256) {
        const int r = idx >> 4, d4 = idx & 15;
        ((float4*)(qs + r * DHH))[d4] =
            ((const float4*)(qbase + (size_t)(t0 + r) * DM))[d4];
    }
    // load K/V tiles (rows t0-63 .. t0+64), zero-pad out-of-range
    for (int idx = tid; idx < KTILE * (DHH / 4); idx += 256) {
        const int r = idx >> 4, d4 = idx & 15;
        const int tk = t0 - (WW - 1) + r;
        float4 kvv = make_float4(0.f, 0.f, 0.f, 0.f);
        float4 vvv = kvv;
        if (tk >= 0 && tk < TT) {
            kvv = ((const float4*)(kbase + (size_t)tk * (2 * DM)))[d4];
            vvv = ((const float4*)(vbase + (size_t)tk * (2 * DM)))[d4];
        }
        ((float4*)(ks + r * KS_LD))[d4] = kvv;
        ((float4*)(vs + r * DHH))[d4] = vvv;
    }
    __syncthreads();

    // scores + sigmoid: key for (qi, w) is local row (qi + w)
    const float SCALE = 0.125f;                 // DH^-0.5
    const float LOGW  = 4.1588830833596718f;    // log(64)
    for (int idx = tid; idx < QTILE * WW; idx += 256) {
        const int qi = idx >> 6, w = idx & 63;
        const float4* qr = (const float4*)(qs + qi * DHH);
        const float4* kr = (const float4*)(ks + (qi + w) * KS_LD);
        float acc = 0.f;
#pragma unroll
        for (int d = 0; d < DHH / 4; d++) {
            float4 qa = qr[d], ka = kr[d];
            acc = fmaf(qa.x, ka.x, acc);
            acc = fmaf(qa.y, ka.y, acc);
            acc = fmaf(qa.z, ka.z, acc);
            acc = fmaf(qa.w, ka.w, acc);
        }
        const float val = acc * SCALE - LOGW;
        const float sg = 1.f / (1.f + __expf(-val));
        const bool mk = mask[(size_t)b * TT + t0 + qi] != 0;   // mask is int32
        ss[qi * WW + w] = mk ? sg : 0.f;
    }
    __syncthreads();

    // out[qi][d] = sum_w ss[qi][w] * vs[qi+w][d]
    float* cbase = ctx + ((size_t)b * TT + t0) * DM + h * DHH;
    for (int idx = tid; idx < QTILE * DHH; idx += 256) {
        const int qi = idx >> 6, d = idx & 63;
        const float* sr = ss + qi * WW;
        float acc = 0.f;
#pragma unroll
        for (int w = 0; w < WW; w++) acc = fmaf(sr[w], vs[(qi + w) * DHH + d], acc);
        cbase[(size_t)qi * DM + d] = acc;
    }
}

// ---------------------------------------------------------------------------
// Launch
// ---------------------------------------------------------------------------
extern "C" void kernel_launch(void* const* d_in, const int* in_sizes, int n_in,
                              void* d_out, int out_size)
{
    const float* x    = (const float*)d_in[0];
    const int* mk     = (const int*)d_in[1];     // bool delivered as int32
    const float* Wq   = (const float*)d_in[2];
    const float* Wkv  = (const float*)d_in[3];
    const float* Wlin = (const float*)d_in[4];
    const float* blin = (const float*)d_in[5];
    float* out        = (float*)d_out;

    void *pq, *pkv, *pctx;
    cudaGetSymbolAddress(&pq, g_q);
    cudaGetSymbolAddress(&pkv, g_kv);
    cudaGetSymbolAddress(&pctx, g_ctx);
    float* q   = (float*)pq;
    float* kv  = (float*)pkv;
    float* ctx = (float*)pctx;

    // Q projection: (4096 x 512) = x (4096x512) * Wq^T
    {
        dim3 grid(DM / BN, NTOK / BM);
        sgemm_kernel<<<grid, 256>>>(x, Wq, q, NTOK, DM, QDIM, nullptr);
    }
    // KV projection: (4096 x 1024)
    {
        dim3 grid((2 * DM) / BN, NTOK / BM);
        sgemm_kernel<<<grid, 256>>>(x, Wkv, kv, NTOK, 2 * DM, QDIM, nullptr);
    }
    // RoPE on q and k halves
    rope_kernel<<<NTOK, 256>>>(q, kv);

    // Attention
    {
        const int smem = (QTILE * DHH + KTILE * KS_LD + KTILE * DHH + QTILE * WW) * (int)sizeof(float);
        cudaFuncSetAttribute(attn_kernel, cudaFuncAttributeMaxDynamicSharedMemorySize, smem);
        dim3 grid(TT / QTILE, HH, BB);
        attn_kernel<<<grid, 256, smem>>>(q, kv, mk, ctx);
    }

    // Output projection + bias
    {
        dim3 grid(DM / BN, NTOK / BM);
        sgemm_kernel<<<grid, 256>>>(ctx, Wlin, out, NTOK, DM, QDIM, blin);
    }
}

// round 5
// speedup vs baseline: 1.4869x; 1.4869x over previous
#include <cuda_runtime.h>
#include <cuda_bf16.h>
#include <cstdint>

// Problem constants
#define BB 2
#define TT 2048
#define QDIM 512
#define HH 8
#define DHH 64
#define WW 64
#define DM 512          // H*DH
#define NTOK (BB*TT)    // 4096

// Split-bf16 GEMM constants: K' = 3*512 (hi|hi|lo vs hi|lo|hi)
#define GK 1536
#define KT 32            // k-tile (bf16 cols) per pipeline stage
#define NKT (GK/KT)      // 48
#define ROWB 80          // padded SMEM row bytes (64B data + 16B pad; conflict-free)
#define ASTG (128*ROWB)  // 10240 bytes per operand per stage
#define STGB (2*ASTG)    // 20480 per stage (A+B)
#define NSTG 3

// Scratch (static device globals; no allocs allowed)
__device__ float g_q[NTOK * DM];
__device__ float g_kv[NTOK * 2 * DM];
__device__ float g_ctx[NTOK * DM];
__device__ __nv_bfloat16 g_xs[(size_t)NTOK * GK];      // split x (A pattern)
__device__ __nv_bfloat16 g_ctxs[(size_t)NTOK * GK];    // split ctx (A pattern)
__device__ __nv_bfloat16 g_wqs[(size_t)DM * GK];       // split Wq (B pattern)
__device__ __nv_bfloat16 g_wkvs[(size_t)2 * DM * GK];  // split Wkv (B pattern)
__device__ __nv_bfloat16 g_wlins[(size_t)DM * GK];     // split Wlin (B pattern)

__device__ __forceinline__ uint32_t smem_u32(const void* p) {
    uint32_t a;
    asm("{ .reg .u64 t; cvta.to.shared.u64 t, %1; cvt.u32.u64 %0, t; }" : "=r"(a) : "l"(p));
    return a;
}

// ---------------------------------------------------------------------------
// Split kernel: f32 [R,512] -> bf16 [R,1536].
// A pattern (bpat=0): [hi | hi | lo].  B pattern (bpat=1): [hi | lo | hi].
// ---------------------------------------------------------------------------
__global__ void split_kernel(const float* __restrict__ in,
                             __nv_bfloat16* __restrict__ out,
                             int total, int bpat)
{
    int i = blockIdx.x * blockDim.x + threadIdx.x;
    if (i >= total) return;
    const int r = i >> 9, c = i & 511;
    const float a = in[i];
    const __nv_bfloat16 h = __float2bfloat16_rn(a);
    const __nv_bfloat16 l = __float2bfloat16_rn(a - __bfloat162float(h));
    const size_t base = (size_t)r * GK + c;
    out[base] = h;
    if (bpat) { out[base + 512] = l; out[base + 1024] = h; }
    else      { out[base + 512] = h; out[base + 1024] = l; }
}

// ---------------------------------------------------------------------------
// mma.sync bf16 GEMM: C[M,N] = A'[M,GK] . B'[N,GK]^T (+bias), fp32 accum.
// Block 128x128, 256 threads (8 warps, 4x2), warp tile 32x64.
// 3-stage cp.async pipeline, KT=32.
// ---------------------------------------------------------------------------
__global__ __launch_bounds__(256, 1) void gemm_mma(
    const __nv_bfloat16* __restrict__ A,
    const __nv_bfloat16* __restrict__ B,
    float* __restrict__ C, int Ntot,
    const float* __restrict__ bias)
{
    extern __shared__ char smem[];
    const uint32_t sbase = smem_u32(smem);

    const int tid  = threadIdx.x;
    const int lane = tid & 31;
    const int warp = tid >> 5;
    const int wm   = warp & 3;          // 4 warps along M (32 rows each)
    const int wn   = warp >> 2;         // 2 warps along N (64 cols each)
    const int m0   = blockIdx.y * 128;
    const int n0   = blockIdx.x * 128;

    // cp.async thread mapping: 512 chunks (16B) per operand per stage;
    // thread handles rows (tid>>2) and (tid>>2)+64, chunk j = tid&3.
    const int ldRow = tid >> 2;         // 0..63
    const int ldJ   = tid & 3;          // 16B chunk within 64B row
    const __nv_bfloat16* gA0 = A + (size_t)(m0 + ldRow) * GK + ldJ * 8;
    const __nv_bfloat16* gA1 = A + (size_t)(m0 + ldRow + 64) * GK + ldJ * 8;
    const __nv_bfloat16* gB0 = B + (size_t)(n0 + ldRow) * GK + ldJ * 8;
    const __nv_bfloat16* gB1 = B + (size_t)(n0 + ldRow + 64) * GK + ldJ * 8;
    const uint32_t sRow0 = ldRow * ROWB + ldJ * 16;
    const uint32_t sRow1 = (ldRow + 64) * ROWB + ldJ * 16;

    float c[2][8][4];
#pragma unroll
    for (int i = 0; i < 2; i++)
#pragma unroll
        for (int j = 0; j < 8; j++)
#pragma unroll
            for (int k = 0; k < 4; k++) c[i][j][k] = 0.f;

    // issue one stage's loads
    auto issue = [&](int stage, int kt) {
        const uint32_t sa = sbase + stage * STGB;
        const uint32_t sb = sa + ASTG;
        const size_t ko = (size_t)kt * KT;
        asm volatile("cp.async.cg.shared.global [%0], [%1], 16;"
                     :: "r"(sa + sRow0), "l"(gA0 + ko) : "memory");
        asm volatile("cp.async.cg.shared.global [%0], [%1], 16;"
                     :: "r"(sa + sRow1), "l"(gA1 + ko) : "memory");
        asm volatile("cp.async.cg.shared.global [%0], [%1], 16;"
                     :: "r"(sb + sRow0), "l"(gB0 + ko) : "memory");
        asm volatile("cp.async.cg.shared.global [%0], [%1], 16;"
                     :: "r"(sb + sRow1), "l"(gB1 + ko) : "memory");
        asm volatile("cp.async.commit_group;" ::: "memory");
    };

    // prologue: stages 0,1
    issue(0, 0);
    issue(1, 1);

    // ldmatrix row/col offsets (constant per thread)
    const uint32_t aRowOff = (uint32_t)(wm * 32 + (lane & 15)) * ROWB
                           + ((lane >> 4) << 4);                 // +16B if lane>=16
    const uint32_t bRowOff = (uint32_t)(wn * 64 + (lane & 7) + ((lane & 16) >> 1)) * ROWB
                           + ((lane & 8) << 1);                  // +16B if lane&8

    for (int kt = 0; kt < NKT; kt++) {
        if (kt < NKT - 2) asm volatile("cp.async.wait_group 1;" ::: "memory");
        else              asm volatile("cp.async.wait_group 0;" ::: "memory");
        __syncthreads();

        const int stage = kt % NSTG;
        const uint32_t sa = sbase + stage * STGB;
        const uint32_t sb = sa + ASTG;

#pragma unroll
        for (int ks = 0; ks < 2; ks++) {
            uint32_t a[2][4];
#pragma unroll
            for (int mt = 0; mt < 2; mt++) {
                const uint32_t addr = sa + aRowOff + mt * 16 * ROWB + ks * 32;
                asm volatile("ldmatrix.sync.aligned.m8n8.x4.shared.b16 {%0,%1,%2,%3}, [%4];"
                             : "=r"(a[mt][0]), "=r"(a[mt][1]), "=r"(a[mt][2]), "=r"(a[mt][3])
                             : "r"(addr));
            }
            uint32_t b[4][4];
#pragma unroll
            for (int p = 0; p < 4; p++) {
                const uint32_t addr = sb + bRowOff + p * 16 * ROWB + ks * 32;
                asm volatile("ldmatrix.sync.aligned.m8n8.x4.shared.b16 {%0,%1,%2,%3}, [%4];"
                             : "=r"(b[p][0]), "=r"(b[p][1]), "=r"(b[p][2]), "=r"(b[p][3])
                             : "r"(addr));
            }
#pragma unroll
            for (int mt = 0; mt < 2; mt++)
#pragma unroll
                for (int nt = 0; nt < 8; nt++) {
                    const int p = nt >> 1, q = (nt & 1) * 2;
                    asm volatile(
                        "mma.sync.aligned.m16n8k16.row.col.f32.bf16.bf16.f32 "
                        "{%0,%1,%2,%3}, {%4,%5,%6,%7}, {%8,%9}, {%0,%1,%2,%3};"
                        : "+f"(c[mt][nt][0]), "+f"(c[mt][nt][1]),
                          "+f"(c[mt][nt][2]), "+f"(c[mt][nt][3])
                        : "r"(a[mt][0]), "r"(a[mt][1]), "r"(a[mt][2]), "r"(a[mt][3]),
                          "r"(b[p][q]), "r"(b[p][q + 1]));
                }
        }

        if (kt + 2 < NKT) issue((kt + 2) % NSTG, kt + 2);
    }

    // epilogue: thread owns rows lane/4 (+8), cols (lane%4)*2 (+1) of each frag
#pragma unroll
    for (int mt = 0; mt < 2; mt++) {
        const int gm = m0 + wm * 32 + mt * 16 + (lane >> 2);
#pragma unroll
        for (int nt = 0; nt < 8; nt++) {
            const int gn = n0 + wn * 64 + nt * 8 + (lane & 3) * 2;
            float2 v0 = make_float2(c[mt][nt][0], c[mt][nt][1]);
            float2 v1 = make_float2(c[mt][nt][2], c[mt][nt][3]);
            if (bias) {
                const float b0 = bias[gn], b1 = bias[gn + 1];
                v0.x += b0; v0.y += b1;
                v1.x += b0; v1.y += b1;
            }
            *(float2*)&C[(size_t)gm * Ntot + gn]       = v0;
            *(float2*)&C[(size_t)(gm + 8) * Ntot + gn] = v1;
        }
    }
}

// ---------------------------------------------------------------------------
// RoPE over the full 512-dim projection: pairs (i, i+256), i in [0,256).
// ---------------------------------------------------------------------------
__global__ void rope_kernel(float* __restrict__ q, float* __restrict__ kv)
{
    const int row = blockIdx.x;
    const int i = threadIdx.x;
    const int t = row & (TT - 1);

    const float inv = powf(100.0f, -(float)i * (1.0f / 256.0f));
    const float ang = (float)t * inv;
    float s, c;
    sincosf(ang, &s, &c);

    float* qr = q + (size_t)row * DM;
    float x1 = qr[i], x2 = qr[i + 256];
    qr[i]       = x1 * c - x2 * s;
    qr[i + 256] = x2 * c + x1 * s;

    float* kr = kv + (size_t)row * (2 * DM);
    x1 = kr[i]; x2 = kr[i + 256];
    kr[i]       = x1 * c - x2 * s;
    kr[i + 256] = x2 * c + x1 * s;
}

// ---------------------------------------------------------------------------
// Sliding-window sigmoid attention (unchanged from R3 passing version).
// Head h: K = concat[128h : 128h+64], V = concat[128h+64 : 128h+128].
// ---------------------------------------------------------------------------
#define QTILE 64
#define KTILE 128
#define KS_LD 68

__global__ __launch_bounds__(256) void attn_kernel(
    const float* __restrict__ q, const float* __restrict__ kv,
    const int* __restrict__ mask, float* __restrict__ ctx)
{
    const int t0 = blockIdx.x * QTILE;
    const int h  = blockIdx.y;
    const int b  = blockIdx.z;

    extern __shared__ float sm[];
    float* qs = sm;
    float* ks = qs + QTILE * DHH;
    float* vs = ks + KTILE * KS_LD;
    float* ss = vs + KTILE * DHH;

    const int tid = threadIdx.x;

    const float* qbase = q + ((size_t)b * TT) * DM + h * DHH;
    const float* kbase = kv + ((size_t)b * TT) * (2 * DM) + h * 128;
    const float* vbase = kbase + 64;

    for (int idx = tid; idx < QTILE * (DHH / 4); idx += 256) {
        const int r = idx >> 4, d4 = idx & 15;
        ((float4*)(qs + r * DHH))[d4] =
            ((const float4*)(qbase + (size_t)(t0 + r) * DM))[d4];
    }
    for (int idx = tid; idx < KTILE * (DHH / 4); idx += 256) {
        const int r = idx >> 4, d4 = idx & 15;
        const int tk = t0 - (WW - 1) + r;
        float4 kvv = make_float4(0.f, 0.f, 0.f, 0.f);
        float4 vvv = kvv;
        if (tk >= 0 && tk < TT) {
            kvv = ((const float4*)(kbase + (size_t)tk * (2 * DM)))[d4];
            vvv = ((const float4*)(vbase + (size_t)tk * (2 * DM)))[d4];
        }
        ((float4*)(ks + r * KS_LD))[d4] = kvv;
        ((float4*)(vs + r * DHH))[d4] = vvv;
    }
    __syncthreads();

    const float SCALE = 0.125f;
    const float LOGW  = 4.1588830833596718f;
    for (int idx = tid; idx < QTILE * WW; idx += 256) {
        const int qi = idx >> 6, w = idx & 63;
        const float4* qr = (const float4*)(qs + qi * DHH);
        const float4* kr = (const float4*)(ks + (qi + w) * KS_LD);
        float acc = 0.f;
#pragma unroll
        for (int d = 0; d < DHH / 4; d++) {
            float4 qa = qr[d], ka = kr[d];
            acc = fmaf(qa.x, ka.x, acc);
            acc = fmaf(qa.y, ka.y, acc);
            acc = fmaf(qa.z, ka.z, acc);
            acc = fmaf(qa.w, ka.w, acc);
        }
        const float val = acc * SCALE - LOGW;
        const float sg = 1.f / (1.f + __expf(-val));
        const bool mk = mask[(size_t)b * TT + t0 + qi] != 0;
        ss[qi * WW + w] = mk ? sg : 0.f;
    }
    __syncthreads();

    float* cbase = ctx + ((size_t)b * TT + t0) * DM + h * DHH;
    for (int idx = tid; idx < QTILE * DHH; idx += 256) {
        const int qi = idx >> 6, d = idx & 63;
        const float* sr = ss + qi * WW;
        float acc = 0.f;
#pragma unroll
        for (int w = 0; w < WW; w++) acc = fmaf(sr[w], vs[(qi + w) * DHH + d], acc);
        cbase[(size_t)qi * DM + d] = acc;
    }
}

// ---------------------------------------------------------------------------
// Launch
// ---------------------------------------------------------------------------
extern "C" void kernel_launch(void* const* d_in, const int* in_sizes, int n_in,
                              void* d_out, int out_size)
{
    const float* x    = (const float*)d_in[0];
    const int* mk     = (const int*)d_in[1];     // bool delivered as int32
    const float* Wq   = (const float*)d_in[2];
    const float* Wkv  = (const float*)d_in[3];
    const float* Wlin = (const float*)d_in[4];
    const float* blin = (const float*)d_in[5];
    float* out        = (float*)d_out;

    void *pq, *pkv, *pctx, *pxs, *pctxs, *pwqs, *pwkvs, *pwlins;
    cudaGetSymbolAddress(&pq, g_q);
    cudaGetSymbolAddress(&pkv, g_kv);
    cudaGetSymbolAddress(&pctx, g_ctx);
    cudaGetSymbolAddress(&pxs, g_xs);
    cudaGetSymbolAddress(&pctxs, g_ctxs);
    cudaGetSymbolAddress(&pwqs, g_wqs);
    cudaGetSymbolAddress(&pwkvs, g_wkvs);
    cudaGetSymbolAddress(&pwlins, g_wlins);
    float* q   = (float*)pq;
    float* kv  = (float*)pkv;
    float* ctx = (float*)pctx;
    __nv_bfloat16* xs    = (__nv_bfloat16*)pxs;
    __nv_bfloat16* ctxs  = (__nv_bfloat16*)pctxs;
    __nv_bfloat16* wqs   = (__nv_bfloat16*)pwqs;
    __nv_bfloat16* wkvs  = (__nv_bfloat16*)pwkvs;
    __nv_bfloat16* wlins = (__nv_bfloat16*)pwlins;

    const int gemm_smem = NSTG * STGB;   // 61440
    cudaFuncSetAttribute(gemm_mma, cudaFuncAttributeMaxDynamicSharedMemorySize, gemm_smem);

    // splits
    split_kernel<<<(NTOK * 512 + 255) / 256, 256>>>(x, xs, NTOK * 512, 0);
    split_kernel<<<(DM * 512 + 255) / 256, 256>>>(Wq, wqs, DM * 512, 1);
    split_kernel<<<(2 * DM * 512 + 255) / 256, 256>>>(Wkv, wkvs, 2 * DM * 512, 1);
    split_kernel<<<(DM * 512 + 255) / 256, 256>>>(Wlin, wlins, DM * 512, 1);

    // Q projection: 4096 x 512
    {
        dim3 grid(DM / 128, NTOK / 128);
        gemm_mma<<<grid, 256, gemm_smem>>>(xs, wqs, q, DM, nullptr);
    }
    // KV projection: 4096 x 1024
    {
        dim3 grid((2 * DM) / 128, NTOK / 128);
        gemm_mma<<<grid, 256, gemm_smem>>>(xs, wkvs, kv, 2 * DM, nullptr);
    }
    // RoPE
    rope_kernel<<<NTOK, 256>>>(q, kv);

    // Attention
    {
        const int smem = (QTILE * DHH + KTILE * KS_LD + KTILE * DHH + QTILE * WW) * (int)sizeof(float);
        cudaFuncSetAttribute(attn_kernel, cudaFuncAttributeMaxDynamicSharedMemorySize, smem);
        dim3 grid(TT / QTILE, HH, BB);
        attn_kernel<<<grid, 256, smem>>>(q, kv, mk, ctx);
    }

    // split ctx, then output projection + bias
    split_kernel<<<(NTOK * 512 + 255) / 256, 256>>>(ctx, ctxs, NTOK * 512, 0);
    {
        dim3 grid(DM / 128, NTOK / 128);
        gemm_mma<<<grid, 256, gemm_smem>>>(ctxs, wlins, out, DM, blin);
    }
}

// round 6
// speedup vs baseline: 1.8102x; 1.2175x over previous
#include <cuda_runtime.h>
#include <cuda_bf16.h>
#include <cstdint>

// Problem constants
#define BB 2
#define TT 2048
#define QDIM 512
#define HH 8
#define DHH 64
#define WW 64
#define DM 512          // H*DH
#define NTOK (BB*TT)    // 4096

// Split-bf16 GEMM constants: K' = 3*512 (hi|hi|lo vs hi|lo|hi)
#define GK 1536
#define KT 32            // k-tile (bf16 cols) per pipeline stage
#define NKT (GK/KT)      // 48
#define ROWB 80          // padded SMEM row bytes (64B data + 16B pad; conflict-free)
#define ASTG (128*ROWB)  // 10240 bytes per operand per stage
#define STGB (2*ASTG)    // 20480 per stage (A+B)
#define NSTG 3

// Scratch (static device globals; no allocs allowed)
__device__ float g_qkv[(size_t)NTOK * 1536];            // [q | k_p | v_p] per token
__device__ __nv_bfloat16 g_xs[(size_t)NTOK * GK];       // split x (A pattern)
__device__ __nv_bfloat16 g_ctxs[(size_t)NTOK * GK];     // split ctx (A pattern)
__device__ __nv_bfloat16 g_wqkv[(size_t)1536 * GK];     // split [Wq;Wkv] (B pattern)
__device__ __nv_bfloat16 g_wlins[(size_t)DM * GK];      // split Wlin (B pattern)

__device__ __forceinline__ uint32_t smem_u32(const void* p) {
    uint32_t a;
    asm("{ .reg .u64 t; cvta.to.shared.u64 t, %1; cvt.u32.u64 %0, t; }" : "=r"(a) : "l"(p));
    return a;
}

// ---------------------------------------------------------------------------
// Fused split kernel: x -> xs (A pattern), Wq/Wkv -> wqkv rows 0..1535 and
// Wlin -> wlins (B pattern). One launch for all pre-GEMM conversions.
// A pattern: [hi | hi | lo].  B pattern: [hi | lo | hi].
// ---------------------------------------------------------------------------
#define NX (NTOK*512)
#define NQ (512*512)
#define NKV2 (1024*512)
#define NL (512*512)

__global__ void split_all(const float* __restrict__ x,
                          const float* __restrict__ Wq,
                          const float* __restrict__ Wkv,
                          const float* __restrict__ Wlin,
                          __nv_bfloat16* __restrict__ xs,
                          __nv_bfloat16* __restrict__ wqkv,
                          __nv_bfloat16* __restrict__ wlins)
{
    const int i = blockIdx.x * blockDim.x + threadIdx.x;
    float a;
    __nv_bfloat16* out;
    int r, c, bpat;
    if (i < NX) {
        a = x[i]; r = i >> 9; c = i & 511; out = xs; bpat = 0;
    } else if (i < NX + NQ) {
        const int j = i - NX;
        a = Wq[j]; r = j >> 9; c = j & 511; out = wqkv; bpat = 1;
    } else if (i < NX + NQ + NKV2) {
        const int j = i - NX - NQ;
        a = Wkv[j]; r = 512 + (j >> 9); c = j & 511; out = wqkv; bpat = 1;
    } else if (i < NX + NQ + NKV2 + NL) {
        const int j = i - NX - NQ - NKV2;
        a = Wlin[j]; r = j >> 9; c = j & 511; out = wlins; bpat = 1;
    } else return;

    const __nv_bfloat16 h = __float2bfloat16_rn(a);
    const __nv_bfloat16 l = __float2bfloat16_rn(a - __bfloat162float(h));
    const size_t base = (size_t)r * GK + c;
    out[base] = h;
    if (bpat) { out[base + 512] = l; out[base + 1024] = h; }
    else      { out[base + 512] = h; out[base + 1024] = l; }
}

// ---------------------------------------------------------------------------
// mma.sync bf16 GEMM: C[M,N] = A'[M,GK] . B'[N,GK]^T (+bias), fp32 accum.
// Block 128x128, 256 threads (8 warps, 4x2), warp tile 32x64.
// 3-stage cp.async pipeline, KT=32. Occupancy target: 2 CTAs/SM.
// ---------------------------------------------------------------------------
__global__ __launch_bounds__(256, 2) void gemm_mma(
    const __nv_bfloat16* __restrict__ A,
    const __nv_bfloat16* __restrict__ B,
    float* __restrict__ C, int Ntot,
    const float* __restrict__ bias)
{
    extern __shared__ char smem[];
    const uint32_t sbase = smem_u32(smem);

    const int tid  = threadIdx.x;
    const int lane = tid & 31;
    const int warp = tid >> 5;
    const int wm   = warp & 3;          // 4 warps along M (32 rows each)
    const int wn   = warp >> 2;         // 2 warps along N (64 cols each)
    const int m0   = blockIdx.y * 128;
    const int n0   = blockIdx.x * 128;

    const int ldRow = tid >> 2;         // 0..63
    const int ldJ   = tid & 3;          // 16B chunk within 64B row
    const __nv_bfloat16* gA0 = A + (size_t)(m0 + ldRow) * GK + ldJ * 8;
    const __nv_bfloat16* gA1 = A + (size_t)(m0 + ldRow + 64) * GK + ldJ * 8;
    const __nv_bfloat16* gB0 = B + (size_t)(n0 + ldRow) * GK + ldJ * 8;
    const __nv_bfloat16* gB1 = B + (size_t)(n0 + ldRow + 64) * GK + ldJ * 8;
    const uint32_t sRow0 = ldRow * ROWB + ldJ * 16;
    const uint32_t sRow1 = (ldRow + 64) * ROWB + ldJ * 16;

    float c[2][8][4];
#pragma unroll
    for (int i = 0; i < 2; i++)
#pragma unroll
        for (int j = 0; j < 8; j++)
#pragma unroll
            for (int k = 0; k < 4; k++) c[i][j][k] = 0.f;

    auto issue = [&](int stage, int kt) {
        const uint32_t sa = sbase + stage * STGB;
        const uint32_t sb = sa + ASTG;
        const size_t ko = (size_t)kt * KT;
        asm volatile("cp.async.cg.shared.global [%0], [%1], 16;"
                     :: "r"(sa + sRow0), "l"(gA0 + ko) : "memory");
        asm volatile("cp.async.cg.shared.global [%0], [%1], 16;"
                     :: "r"(sa + sRow1), "l"(gA1 + ko) : "memory");
        asm volatile("cp.async.cg.shared.global [%0], [%1], 16;"
                     :: "r"(sb + sRow0), "l"(gB0 + ko) : "memory");
        asm volatile("cp.async.cg.shared.global [%0], [%1], 16;"
                     :: "r"(sb + sRow1), "l"(gB1 + ko) : "memory");
        asm volatile("cp.async.commit_group;" ::: "memory");
    };

    issue(0, 0);
    issue(1, 1);

    const uint32_t aRowOff = (uint32_t)(wm * 32 + (lane & 15)) * ROWB
                           + ((lane >> 4) << 4);
    const uint32_t bRowOff = (uint32_t)(wn * 64 + (lane & 7) + ((lane & 16) >> 1)) * ROWB
                           + ((lane & 8) << 1);

    for (int kt = 0; kt < NKT; kt++) {
        if (kt < NKT - 2) asm volatile("cp.async.wait_group 1;" ::: "memory");
        else              asm volatile("cp.async.wait_group 0;" ::: "memory");
        __syncthreads();

        const int stage = kt % NSTG;
        const uint32_t sa = sbase + stage * STGB;
        const uint32_t sb = sa + ASTG;

#pragma unroll
        for (int ks = 0; ks < 2; ks++) {
            uint32_t a[2][4];
#pragma unroll
            for (int mt = 0; mt < 2; mt++) {
                const uint32_t addr = sa + aRowOff + mt * 16 * ROWB + ks * 32;
                asm volatile("ldmatrix.sync.aligned.m8n8.x4.shared.b16 {%0,%1,%2,%3}, [%4];"
                             : "=r"(a[mt][0]), "=r"(a[mt][1]), "=r"(a[mt][2]), "=r"(a[mt][3])
                             : "r"(addr));
            }
            uint32_t b[4][4];
#pragma unroll
            for (int p = 0; p < 4; p++) {
                const uint32_t addr = sb + bRowOff + p * 16 * ROWB + ks * 32;
                asm volatile("ldmatrix.sync.aligned.m8n8.x4.shared.b16 {%0,%1,%2,%3}, [%4];"
                             : "=r"(b[p][0]), "=r"(b[p][1]), "=r"(b[p][2]), "=r"(b[p][3])
                             : "r"(addr));
            }
#pragma unroll
            for (int mt = 0; mt < 2; mt++)
#pragma unroll
                for (int nt = 0; nt < 8; nt++) {
                    const int p = nt >> 1, q = (nt & 1) * 2;
                    asm volatile(
                        "mma.sync.aligned.m16n8k16.row.col.f32.bf16.bf16.f32 "
                        "{%0,%1,%2,%3}, {%4,%5,%6,%7}, {%8,%9}, {%0,%1,%2,%3};"
                        : "+f"(c[mt][nt][0]), "+f"(c[mt][nt][1]),
                          "+f"(c[mt][nt][2]), "+f"(c[mt][nt][3])
                        : "r"(a[mt][0]), "r"(a[mt][1]), "r"(a[mt][2]), "r"(a[mt][3]),
                          "r"(b[p][q]), "r"(b[p][q + 1]));
                }
        }

        if (kt + 2 < NKT) issue((kt + 2) % NSTG, kt + 2);
    }

#pragma unroll
    for (int mt = 0; mt < 2; mt++) {
        const int gm = m0 + wm * 32 + mt * 16 + (lane >> 2);
#pragma unroll
        for (int nt = 0; nt < 8; nt++) {
            const int gn = n0 + wn * 64 + nt * 8 + (lane & 3) * 2;
            float2 v0 = make_float2(c[mt][nt][0], c[mt][nt][1]);
            float2 v1 = make_float2(c[mt][nt][2], c[mt][nt][3]);
            if (bias) {
                const float b0 = bias[gn], b1 = bias[gn + 1];
                v0.x += b0; v0.y += b1;
                v1.x += b0; v1.y += b1;
            }
            *(float2*)&C[(size_t)gm * Ntot + gn]       = v0;
            *(float2*)&C[(size_t)(gm + 8) * Ntot + gn] = v1;
        }
    }
}

// ---------------------------------------------------------------------------
// RoPE on qkv rows: q = cols [0,512), k_p = cols [512,1024).
// Pairs (i, i+256) within each 512-wide section.
// ---------------------------------------------------------------------------
__global__ void rope_kernel(float* __restrict__ qkv)
{
    const int row = blockIdx.x;
    const int i = threadIdx.x;
    const int t = row & (TT - 1);

    const float inv = powf(100.0f, -(float)i * (1.0f / 256.0f));
    const float ang = (float)t * inv;
    float s, c;
    sincosf(ang, &s, &c);

    float* pr = qkv + (size_t)row * 1536;
    float x1 = pr[i], x2 = pr[i + 256];
    pr[i]       = x1 * c - x2 * s;
    pr[i + 256] = x2 * c + x1 * s;

    x1 = pr[512 + i]; x2 = pr[512 + i + 256];
    pr[512 + i]       = x1 * c - x2 * s;
    pr[512 + i + 256] = x2 * c + x1 * s;
}

// ---------------------------------------------------------------------------
// Sliding-window sigmoid attention. qkv row = [q(512) | concat(1024)] where
// concat = [rope(k_p) | v_p]; head h: K = concat[128h:128h+64],
// V = concat[128h+64:128h+128]. Epilogue writes split-bf16 ctx directly.
// ---------------------------------------------------------------------------
#define QTILE 64
#define KTILE 128
#define KS_LD 68

__global__ __launch_bounds__(256) void attn_kernel(
    const float* __restrict__ qkv,
    const int* __restrict__ mask,
    __nv_bfloat16* __restrict__ ctxs)
{
    const int t0 = blockIdx.x * QTILE;
    const int h  = blockIdx.y;
    const int b  = blockIdx.z;

    extern __shared__ float sm[];
    float* qs = sm;
    float* ks = qs + QTILE * DHH;
    float* vs = ks + KTILE * KS_LD;
    float* ss = vs + KTILE * DHH;

    const int tid = threadIdx.x;

    const float* qbase = qkv + (size_t)b * TT * 1536 + h * DHH;
    const float* kbase = qkv + (size_t)b * TT * 1536 + 512 + h * 128;
    const float* vbase = kbase + 64;

    for (int idx = tid; idx < QTILE * (DHH / 4); idx += 256) {
        const int r = idx >> 4, d4 = idx & 15;
        ((float4*)(qs + r * DHH))[d4] =
            ((const float4*)(qbase + (size_t)(t0 + r) * 1536))[d4];
    }
    for (int idx = tid; idx < KTILE * (DHH / 4); idx += 256) {
        const int r = idx >> 4, d4 = idx & 15;
        const int tk = t0 - (WW - 1) + r;
        float4 kvv = make_float4(0.f, 0.f, 0.f, 0.f);
        float4 vvv = kvv;
        if (tk >= 0 && tk < TT) {
            kvv = ((const float4*)(kbase + (size_t)tk * 1536))[d4];
            vvv = ((const float4*)(vbase + (size_t)tk * 1536))[d4];
        }
        ((float4*)(ks + r * KS_LD))[d4] = kvv;
        ((float4*)(vs + r * DHH))[d4] = vvv;
    }
    __syncthreads();

    const float SCALE = 0.125f;
    const float LOGW  = 4.1588830833596718f;
    for (int idx = tid; idx < QTILE * WW; idx += 256) {
        const int qi = idx >> 6, w = idx & 63;
        const float4* qr = (const float4*)(qs + qi * DHH);
        const float4* kr = (const float4*)(ks + (qi + w) * KS_LD);
        float acc = 0.f;
#pragma unroll
        for (int d = 0; d < DHH / 4; d++) {
            float4 qa = qr[d], ka = kr[d];
            acc = fmaf(qa.x, ka.x, acc);
            acc = fmaf(qa.y, ka.y, acc);
            acc = fmaf(qa.z, ka.z, acc);
            acc = fmaf(qa.w, ka.w, acc);
        }
        const float val = acc * SCALE - LOGW;
        const float sg = 1.f / (1.f + __expf(-val));
        const bool mk = mask[(size_t)b * TT + t0 + qi] != 0;
        ss[qi * WW + w] = mk ? sg : 0.f;
    }
    __syncthreads();

    // out[qi][d] = sum_w ss[qi][w] * vs[qi+w][d]; write split bf16 (A pattern)
    for (int idx = tid; idx < QTILE * DHH; idx += 256) {
        const int qi = idx >> 6, d = idx & 63;
        const float* sr = ss + qi * WW;
        float acc = 0.f;
#pragma unroll
        for (int w = 0; w < WW; w++) acc = fmaf(sr[w], vs[(qi + w) * DHH + d], acc);
        const __nv_bfloat16 hi = __float2bfloat16_rn(acc);
        const __nv_bfloat16 lo = __float2bfloat16_rn(acc - __bfloat162float(hi));
        const size_t base = (size_t)(b * TT + t0 + qi) * GK + h * DHH + d;
        ctxs[base]        = hi;
        ctxs[base + 512]  = hi;
        ctxs[base + 1024] = lo;
    }
}

// ---------------------------------------------------------------------------
// Launch
// ---------------------------------------------------------------------------
extern "C" void kernel_launch(void* const* d_in, const int* in_sizes, int n_in,
                              void* d_out, int out_size)
{
    const float* x    = (const float*)d_in[0];
    const int* mk     = (const int*)d_in[1];     // bool delivered as int32
    const float* Wq   = (const float*)d_in[2];
    const float* Wkv  = (const float*)d_in[3];
    const float* Wlin = (const float*)d_in[4];
    const float* blin = (const float*)d_in[5];
    float* out        = (float*)d_out;

    void *pqkv, *pxs, *pctxs, *pwqkv, *pwlins;
    cudaGetSymbolAddress(&pqkv, g_qkv);
    cudaGetSymbolAddress(&pxs, g_xs);
    cudaGetSymbolAddress(&pctxs, g_ctxs);
    cudaGetSymbolAddress(&pwqkv, g_wqkv);
    cudaGetSymbolAddress(&pwlins, g_wlins);
    float* qkv = (float*)pqkv;
    __nv_bfloat16* xs    = (__nv_bfloat16*)pxs;
    __nv_bfloat16* ctxs  = (__nv_bfloat16*)pctxs;
    __nv_bfloat16* wqkv  = (__nv_bfloat16*)pwqkv;
    __nv_bfloat16* wlins = (__nv_bfloat16*)pwlins;

    const int gemm_smem = NSTG * STGB;   // 61440
    cudaFuncSetAttribute(gemm_mma, cudaFuncAttributeMaxDynamicSharedMemorySize, gemm_smem);

    // one fused split for all pre-GEMM conversions
    {
        const int total = NX + NQ + NKV2 + NL;
        split_all<<<(total + 255) / 256, 256>>>(x, Wq, Wkv, Wlin, xs, wqkv, wlins);
    }

    // fused Q+KV projection: 4096 x 1536
    {
        dim3 grid(1536 / 128, NTOK / 128);
        gemm_mma<<<grid, 256, gemm_smem>>>(xs, wqkv, qkv, 1536, nullptr);
    }
    // RoPE on q and k_p sections
    rope_kernel<<<NTOK, 256>>>(qkv);

    // Attention (writes split-bf16 ctx directly)
    {
        const int smem = (QTILE * DHH + KTILE * KS_LD + KTILE * DHH + QTILE * WW) * (int)sizeof(float);
        cudaFuncSetAttribute(attn_kernel, cudaFuncAttributeMaxDynamicSharedMemorySize, smem);
        dim3 grid(TT / QTILE, HH, BB);
        attn_kernel<<<grid, 256, smem>>>(qkv, mk, ctxs);
    }

    // output projection + bias
    {
        dim3 grid(DM / 128, NTOK / 128);
        gemm_mma<<<grid, 256, gemm_smem>>>(ctxs, wlins, out, DM, blin);
    }
}

// round 7
// speedup vs baseline: 2.0848x; 1.1517x over previous
#include <cuda_runtime.h>
#include <cuda_bf16.h>
#include <cstdint>

// Problem constants
#define BB 2
#define TT 2048
#define QDIM 512
#define HH 8
#define DHH 64
#define WW 64
#define DM 512          // H*DH
#define NTOK (BB*TT)    // 4096

// Split-bf16 GEMM constants: K' = 3*512 (hi|hi|lo vs hi|lo|hi)
#define GK 1536
#define KT 32            // k-tile (bf16 cols) per pipeline stage
#define NKT (GK/KT)      // 48
#define ROWB 80          // padded SMEM row bytes (64B data + 16B pad; conflict-free)
#define ASTG (128*ROWB)  // 10240 bytes per operand per stage
#define STGB (2*ASTG)    // 20480 per stage (A+B)
#define NSTG 3

// Scratch (static device globals; no allocs allowed)
__device__ float g_qkv[(size_t)NTOK * 1536];            // [q | k_p | v_p] per token
__device__ __nv_bfloat16 g_xs[(size_t)NTOK * GK];       // split x (A pattern)
__device__ __nv_bfloat16 g_ctxs[(size_t)NTOK * GK];     // split ctx (A pattern)
__device__ __nv_bfloat16 g_wqkv[(size_t)1536 * GK];     // split [Wq;Wkv] (B pattern)
__device__ __nv_bfloat16 g_wlins[(size_t)DM * GK];      // split Wlin (B pattern)

__device__ __forceinline__ uint32_t smem_u32(const void* p) {
    uint32_t a;
    asm("{ .reg .u64 t; cvta.to.shared.u64 t, %1; cvt.u32.u64 %0, t; }" : "=r"(a) : "l"(p));
    return a;
}

// pack two f32 into bf16x2 (lo in low half, hi arg in high half)
__device__ __forceinline__ uint32_t packbf2(float lo, float hi) {
    uint32_t d;
    asm("cvt.rn.bf16x2.f32 %0, %1, %2;" : "=r"(d) : "f"(hi), "f"(lo));
    return d;
}

__device__ __forceinline__ void ldsm4(uint32_t r[4], uint32_t addr) {
    asm volatile("ldmatrix.sync.aligned.m8n8.x4.shared.b16 {%0,%1,%2,%3}, [%4];"
                 : "=r"(r[0]), "=r"(r[1]), "=r"(r[2]), "=r"(r[3]) : "r"(addr));
}
__device__ __forceinline__ void ldsm4t(uint32_t r[4], uint32_t addr) {
    asm volatile("ldmatrix.sync.aligned.m8n8.x4.trans.shared.b16 {%0,%1,%2,%3}, [%4];"
                 : "=r"(r[0]), "=r"(r[1]), "=r"(r[2]), "=r"(r[3]) : "r"(addr));
}
__device__ __forceinline__ void mma16816(float c[4], const uint32_t a[4],
                                         uint32_t b0, uint32_t b1) {
    asm volatile(
        "mma.sync.aligned.m16n8k16.row.col.f32.bf16.bf16.f32 "
        "{%0,%1,%2,%3}, {%4,%5,%6,%7}, {%8,%9}, {%0,%1,%2,%3};"
        : "+f"(c[0]), "+f"(c[1]), "+f"(c[2]), "+f"(c[3])
        : "r"(a[0]), "r"(a[1]), "r"(a[2]), "r"(a[3]), "r"(b0), "r"(b1));
}

// ---------------------------------------------------------------------------
// Fused split kernel (pre-GEMM conversions, one launch).
// A pattern: [hi | hi | lo].  B pattern: [hi | lo | hi].
// ---------------------------------------------------------------------------
#define NX (NTOK*512)
#define NQ (512*512)
#define NKV2 (1024*512)
#define NL (512*512)

__global__ void split_all(const float* __restrict__ x,
                          const float* __restrict__ Wq,
                          const float* __restrict__ Wkv,
                          const float* __restrict__ Wlin,
                          __nv_bfloat16* __restrict__ xs,
                          __nv_bfloat16* __restrict__ wqkv,
                          __nv_bfloat16* __restrict__ wlins)
{
    const int i = blockIdx.x * blockDim.x + threadIdx.x;
    float a;
    __nv_bfloat16* out;
    int r, c, bpat;
    if (i < NX) {
        a = x[i]; r = i >> 9; c = i & 511; out = xs; bpat = 0;
    } else if (i < NX + NQ) {
        const int j = i - NX;
        a = Wq[j]; r = j >> 9; c = j & 511; out = wqkv; bpat = 1;
    } else if (i < NX + NQ + NKV2) {
        const int j = i - NX - NQ;
        a = Wkv[j]; r = 512 + (j >> 9); c = j & 511; out = wqkv; bpat = 1;
    } else if (i < NX + NQ + NKV2 + NL) {
        const int j = i - NX - NQ - NKV2;
        a = Wlin[j]; r = j >> 9; c = j & 511; out = wlins; bpat = 1;
    } else return;

    const __nv_bfloat16 h = __float2bfloat16_rn(a);
    const __nv_bfloat16 l = __float2bfloat16_rn(a - __bfloat162float(h));
    const size_t base = (size_t)r * GK + c;
    out[base] = h;
    if (bpat) { out[base + 512] = l; out[base + 1024] = h; }
    else      { out[base + 512] = h; out[base + 1024] = l; }
}

// ---------------------------------------------------------------------------
// mma.sync bf16 GEMM (unchanged from R6): C = A'.B'^T (+bias), fp32 accum.
// ---------------------------------------------------------------------------
__global__ __launch_bounds__(256, 2) void gemm_mma(
    const __nv_bfloat16* __restrict__ A,
    const __nv_bfloat16* __restrict__ B,
    float* __restrict__ C, int Ntot,
    const float* __restrict__ bias)
{
    extern __shared__ char smem[];
    const uint32_t sbase = smem_u32(smem);

    const int tid  = threadIdx.x;
    const int lane = tid & 31;
    const int warp = tid >> 5;
    const int wm   = warp & 3;
    const int wn   = warp >> 2;
    const int m0   = blockIdx.y * 128;
    const int n0   = blockIdx.x * 128;

    const int ldRow = tid >> 2;
    const int ldJ   = tid & 3;
    const __nv_bfloat16* gA0 = A + (size_t)(m0 + ldRow) * GK + ldJ * 8;
    const __nv_bfloat16* gA1 = A + (size_t)(m0 + ldRow + 64) * GK + ldJ * 8;
    const __nv_bfloat16* gB0 = B + (size_t)(n0 + ldRow) * GK + ldJ * 8;
    const __nv_bfloat16* gB1 = B + (size_t)(n0 + ldRow + 64) * GK + ldJ * 8;
    const uint32_t sRow0 = ldRow * ROWB + ldJ * 16;
    const uint32_t sRow1 = (ldRow + 64) * ROWB + ldJ * 16;

    float c[2][8][4];
#pragma unroll
    for (int i = 0; i < 2; i++)
#pragma unroll
        for (int j = 0; j < 8; j++)
#pragma unroll
            for (int k = 0; k < 4; k++) c[i][j][k] = 0.f;

    auto issue = [&](int stage, int kt) {
        const uint32_t sa = sbase + stage * STGB;
        const uint32_t sb = sa + ASTG;
        const size_t ko = (size_t)kt * KT;
        asm volatile("cp.async.cg.shared.global [%0], [%1], 16;"
                     :: "r"(sa + sRow0), "l"(gA0 + ko) : "memory");
        asm volatile("cp.async.cg.shared.global [%0], [%1], 16;"
                     :: "r"(sa + sRow1), "l"(gA1 + ko) : "memory");
        asm volatile("cp.async.cg.shared.global [%0], [%1], 16;"
                     :: "r"(sb + sRow0), "l"(gB0 + ko) : "memory");
        asm volatile("cp.async.cg.shared.global [%0], [%1], 16;"
                     :: "r"(sb + sRow1), "l"(gB1 + ko) : "memory");
        asm volatile("cp.async.commit_group;" ::: "memory");
    };

    issue(0, 0);
    issue(1, 1);

    const uint32_t aRowOff = (uint32_t)(wm * 32 + (lane & 15)) * ROWB
                           + ((lane >> 4) << 4);
    const uint32_t bRowOff = (uint32_t)(wn * 64 + (lane & 7) + ((lane & 16) >> 1)) * ROWB
                           + ((lane & 8) << 1);

    for (int kt = 0; kt < NKT; kt++) {
        if (kt < NKT - 2) asm volatile("cp.async.wait_group 1;" ::: "memory");
        else              asm volatile("cp.async.wait_group 0;" ::: "memory");
        __syncthreads();

        const int stage = kt % NSTG;
        const uint32_t sa = sbase + stage * STGB;
        const uint32_t sb = sa + ASTG;

#pragma unroll
        for (int ks = 0; ks < 2; ks++) {
            uint32_t a[2][4];
#pragma unroll
            for (int mt = 0; mt < 2; mt++)
                ldsm4(a[mt], sa + aRowOff + mt * 16 * ROWB + ks * 32);
            uint32_t b[4][4];
#pragma unroll
            for (int p = 0; p < 4; p++)
                ldsm4(b[p], sb + bRowOff + p * 16 * ROWB + ks * 32);
#pragma unroll
            for (int mt = 0; mt < 2; mt++)
#pragma unroll
                for (int nt = 0; nt < 8; nt++) {
                    const int p = nt >> 1, q = (nt & 1) * 2;
                    mma16816(c[mt][nt], a[mt], b[p][q], b[p][q + 1]);
                }
        }

        if (kt + 2 < NKT) issue((kt + 2) % NSTG, kt + 2);
    }

#pragma unroll
    for (int mt = 0; mt < 2; mt++) {
        const int gm = m0 + wm * 32 + mt * 16 + (lane >> 2);
#pragma unroll
        for (int nt = 0; nt < 8; nt++) {
            const int gn = n0 + wn * 64 + nt * 8 + (lane & 3) * 2;
            float2 v0 = make_float2(c[mt][nt][0], c[mt][nt][1]);
            float2 v1 = make_float2(c[mt][nt][2], c[mt][nt][3]);
            if (bias) {
                const float b0 = bias[gn], b1 = bias[gn + 1];
                v0.x += b0; v0.y += b1;
                v1.x += b0; v1.y += b1;
            }
            *(float2*)&C[(size_t)gm * Ntot + gn]       = v0;
            *(float2*)&C[(size_t)(gm + 8) * Ntot + gn] = v1;
        }
    }
}

// ---------------------------------------------------------------------------
// RoPE on qkv rows (cols [0,512) and [512,1024), pairs (i, i+256)).
// ---------------------------------------------------------------------------
__global__ void rope_kernel(float* __restrict__ qkv)
{
    const int row = blockIdx.x;
    const int i = threadIdx.x;
    const int t = row & (TT - 1);

    const float inv = powf(100.0f, -(float)i * (1.0f / 256.0f));
    const float ang = (float)t * inv;
    float s, c;
    sincosf(ang, &s, &c);

    float* pr = qkv + (size_t)row * 1536;
    float x1 = pr[i], x2 = pr[i + 256];
    pr[i]       = x1 * c - x2 * s;
    pr[i + 256] = x2 * c + x1 * s;

    x1 = pr[512 + i]; x2 = pr[512 + i + 256];
    pr[512 + i]       = x1 * c - x2 * s;
    pr[512 + i + 256] = x2 * c + x1 * s;
}

// ---------------------------------------------------------------------------
// MMA sliding-window sigmoid attention.
// Per block: (b, h, 64 q rows). 128 threads (4 warps); warp w owns q rows
// [16w, 16w+16) x all 128 local keys. 3-term split bf16 on both GEMMs.
// K tile rows r=0..127 <-> t = t0-63+r; band: S[qi][r] kept iff 0<=r-qi<=63.
// Head h: K = concat[128h:128h+64], V = concat[128h+64:128h+128].
// ---------------------------------------------------------------------------
#define AT_ROWB 144      // 64 bf16 * 2B + 16 pad (36 words ≡ 4 banks: conflict-free)
#define SM_QHI 0
#define SM_QLO 9216
#define SM_KHI 18432
#define SM_KLO 36864
#define SM_VHI 55296
#define SM_VLO 73728
#define AT_SMEM 92160

__global__ __launch_bounds__(128, 2) void attn_mma(
    const float* __restrict__ qkv,
    const int* __restrict__ mask,
    __nv_bfloat16* __restrict__ ctxs)
{
    extern __shared__ char smem[];
    const uint32_t sb = smem_u32(smem);

    const int t0 = blockIdx.x * 64;
    const int h  = blockIdx.y;
    const int b  = blockIdx.z;
    const int tid  = threadIdx.x;
    const int lane = tid & 31;
    const int warp = tid >> 5;

    const float* qbase = qkv + (size_t)b * TT * 1536 + h * DHH;
    const float* kbase = qkv + (size_t)b * TT * 1536 + 512 + h * 128;
    const float* vbase = kbase + 64;

    // ---- load + split-convert tiles into smem ----
    // Q: 64 rows x 64 dims
    for (int i = tid; i < 64 * 16; i += 128) {
        const int r = i >> 4, d4 = i & 15;
        const float4 f = *(const float4*)(qbase + (size_t)(t0 + r) * 1536 + d4 * 4);
        const float hx = __bfloat162float(__float2bfloat16_rn(f.x));
        const float hy = __bfloat162float(__float2bfloat16_rn(f.y));
        const float hz = __bfloat162float(__float2bfloat16_rn(f.z));
        const float hw = __bfloat162float(__float2bfloat16_rn(f.w));
        uint2 hi = make_uint2(packbf2(f.x, f.y), packbf2(f.z, f.w));
        uint2 lo = make_uint2(packbf2(f.x - hx, f.y - hy), packbf2(f.z - hz, f.w - hw));
        *(uint2*)(smem + SM_QHI + r * AT_ROWB + d4 * 8) = hi;
        *(uint2*)(smem + SM_QLO + r * AT_ROWB + d4 * 8) = lo;
    }
    // K and V: 128 rows x 64 dims (zero-pad out of range)
    for (int i = tid; i < 128 * 16; i += 128) {
        const int r = i >> 4, d4 = i & 15;
        const int tk = t0 - 63 + r;
        float4 fk = make_float4(0.f, 0.f, 0.f, 0.f), fv = fk;
        if (tk >= 0 && tk < TT) {
            fk = *(const float4*)(kbase + (size_t)tk * 1536 + d4 * 4);
            fv = *(const float4*)(vbase + (size_t)tk * 1536 + d4 * 4);
        }
        {
            const float hx = __bfloat162float(__float2bfloat16_rn(fk.x));
            const float hy = __bfloat162float(__float2bfloat16_rn(fk.y));
            const float hz = __bfloat162float(__float2bfloat16_rn(fk.z));
            const float hw = __bfloat162float(__float2bfloat16_rn(fk.w));
            *(uint2*)(smem + SM_KHI + r * AT_ROWB + d4 * 8) =
                make_uint2(packbf2(fk.x, fk.y), packbf2(fk.z, fk.w));
            *(uint2*)(smem + SM_KLO + r * AT_ROWB + d4 * 8) =
                make_uint2(packbf2(fk.x - hx, fk.y - hy), packbf2(fk.z - hz, fk.w - hw));
        }
        {
            const float hx = __bfloat162float(__float2bfloat16_rn(fv.x));
            const float hy = __bfloat162float(__float2bfloat16_rn(fv.y));
            const float hz = __bfloat162float(__float2bfloat16_rn(fv.z));
            const float hw = __bfloat162float(__float2bfloat16_rn(fv.w));
            *(uint2*)(smem + SM_VHI + r * AT_ROWB + d4 * 8) =
                make_uint2(packbf2(fv.x, fv.y), packbf2(fv.z, fv.w));
            *(uint2*)(smem + SM_VLO + r * AT_ROWB + d4 * 8) =
                make_uint2(packbf2(fv.x - hx, fv.y - hy), packbf2(fv.z - hz, fv.w - hw));
        }
    }
    __syncthreads();

    // ---- QK^T: warp tile m16 x n128, K'=64 per pass, 3-term split ----
    const int m0 = warp * 16;
    const uint32_t aOff = (uint32_t)(m0 + (lane & 15)) * AT_ROWB + ((lane >> 4) << 4);
    const uint32_t bOff = (uint32_t)((lane & 7) + ((lane & 16) >> 1)) * AT_ROWB
                        + ((lane & 8) << 1);

    float cs[16][4];
#pragma unroll
    for (int i = 0; i < 16; i++)
#pragma unroll
        for (int j = 0; j < 4; j++) cs[i][j] = 0.f;

#pragma unroll
    for (int ks = 0; ks < 4; ks++) {
        uint32_t ah[4], al[4];
        ldsm4(ah, sb + SM_QHI + aOff + ks * 32);
        ldsm4(al, sb + SM_QLO + aOff + ks * 32);
#pragma unroll
        for (int ng = 0; ng < 8; ng++) {
            uint32_t bh[4], bl[4];
            ldsm4(bh, sb + SM_KHI + ng * (16 * AT_ROWB) + ks * 32 + bOff);
            mma16816(cs[2 * ng],     ah, bh[0], bh[1]);
            mma16816(cs[2 * ng + 1], ah, bh[2], bh[3]);
            mma16816(cs[2 * ng],     al, bh[0], bh[1]);
            mma16816(cs[2 * ng + 1], al, bh[2], bh[3]);
            ldsm4(bl, sb + SM_KLO + ng * (16 * AT_ROWB) + ks * 32 + bOff);
            mma16816(cs[2 * ng],     ah, bl[0], bl[1]);
            mma16816(cs[2 * ng + 1], ah, bl[2], bl[3]);
        }
    }

    // ---- sigmoid + band + mask in registers; split S to bf16 hi/lo pairs ----
    const float SCALE = 0.125f;
    const float LOGW  = 4.1588830833596718f;
    const int qa = m0 + (lane >> 2);       // row for c0,c1
    const int qb = qa + 8;                 // row for c2,c3
    const bool mka = mask[(size_t)b * TT + t0 + qa] != 0;
    const bool mkb = mask[(size_t)b * TT + t0 + qb] != 0;

    uint32_t SH[16][2], SL[16][2];
#pragma unroll
    for (int nt = 0; nt < 16; nt++) {
        const int r0 = nt * 8 + (lane & 3) * 2;
        float s[4];
#pragma unroll
        for (int e = 0; e < 2; e++) {
            const int r = r0 + e;
            // row a
            {
                const int w = r - qa;
                float v = 0.f;
                if (w >= 0 && w < 64 && mka) {
                    const float val = cs[nt][e] * SCALE - LOGW;
                    v = 1.f / (1.f + __expf(-val));
                }
                s[e] = v;
            }
            // row b
            {
                const int w = r - qb;
                float v = 0.f;
                if (w >= 0 && w < 64 && mkb) {
                    const float val = cs[nt][2 + e] * SCALE - LOGW;
                    v = 1.f / (1.f + __expf(-val));
                }
                s[2 + e] = v;
            }
        }
        const float h0 = __bfloat162float(__float2bfloat16_rn(s[0]));
        const float h1 = __bfloat162float(__float2bfloat16_rn(s[1]));
        const float h2 = __bfloat162float(__float2bfloat16_rn(s[2]));
        const float h3 = __bfloat162float(__float2bfloat16_rn(s[3]));
        SH[nt][0] = packbf2(s[0], s[1]);
        SH[nt][1] = packbf2(s[2], s[3]);
        SL[nt][0] = packbf2(s[0] - h0, s[1] - h1);
        SL[nt][1] = packbf2(s[2] - h2, s[3] - h3);
    }

    // ---- PV: C(16x64) = S(16x128) x V(128x64), V via ldmatrix.trans ----
    float co[8][4];
#pragma unroll
    for (int i = 0; i < 8; i++)
#pragma unroll
        for (int j = 0; j < 4; j++) co[i][j] = 0.f;

    const uint32_t vOff = (uint32_t)((lane & 7) + (lane & 8)) * AT_ROWB
                        + ((lane & 16) >> 4) * 16;

#pragma unroll
    for (int ks = 0; ks < 8; ks++) {
        const uint32_t aH[4] = { SH[2*ks][0], SH[2*ks][1], SH[2*ks+1][0], SH[2*ks+1][1] };
        const uint32_t aL[4] = { SL[2*ks][0], SL[2*ks][1], SL[2*ks+1][0], SL[2*ks+1][1] };
        const uint32_t kOff = ks * (16 * AT_ROWB) + vOff;
#pragma unroll
        for (int ng = 0; ng < 4; ng++) {
            uint32_t vh[4], vl[4];
            ldsm4t(vh, sb + SM_VHI + kOff + ng * 32);
            mma16816(co[2 * ng],     aH, vh[0], vh[1]);
            mma16816(co[2 * ng + 1], aH, vh[2], vh[3]);
            mma16816(co[2 * ng],     aL, vh[0], vh[1]);
            mma16816(co[2 * ng + 1], aL, vh[2], vh[3]);
            ldsm4t(vl, sb + SM_VLO + kOff + ng * 32);
            mma16816(co[2 * ng],     aH, vl[0], vl[1]);
            mma16816(co[2 * ng + 1], aH, vl[2], vl[3]);
        }
    }

    // ---- epilogue: write split-bf16 ctx (A pattern: hi, hi, lo) ----
    const size_t rowA = (size_t)(b * TT + t0 + qa) * GK + h * DHH;
    const size_t rowB = (size_t)(b * TT + t0 + qb) * GK + h * DHH;
#pragma unroll
    for (int nt = 0; nt < 8; nt++) {
        const int d = nt * 8 + (lane & 3) * 2;
        const float h0 = __bfloat162float(__float2bfloat16_rn(co[nt][0]));
        const float h1 = __bfloat162float(__float2bfloat16_rn(co[nt][1]));
        const float h2 = __bfloat162float(__float2bfloat16_rn(co[nt][2]));
        const float h3 = __bfloat162float(__float2bfloat16_rn(co[nt][3]));
        const uint32_t hA = packbf2(co[nt][0], co[nt][1]);
        const uint32_t lA = packbf2(co[nt][0] - h0, co[nt][1] - h1);
        const uint32_t hB = packbf2(co[nt][2], co[nt][3]);
        const uint32_t lB = packbf2(co[nt][2] - h2, co[nt][3] - h3);
        *(uint32_t*)(ctxs + rowA + d)        = hA;
        *(uint32_t*)(ctxs + rowA + 512 + d)  = hA;
        *(uint32_t*)(ctxs + rowA + 1024 + d) = lA;
        *(uint32_t*)(ctxs + rowB + d)        = hB;
        *(uint32_t*)(ctxs + rowB + 512 + d)  = hB;
        *(uint32_t*)(ctxs + rowB + 1024 + d) = lB;
    }
}

// ---------------------------------------------------------------------------
// Launch
// ---------------------------------------------------------------------------
extern "C" void kernel_launch(void* const* d_in, const int* in_sizes, int n_in,
                              void* d_out, int out_size)
{
    const float* x    = (const float*)d_in[0];
    const int* mk     = (const int*)d_in[1];     // bool delivered as int32
    const float* Wq   = (const float*)d_in[2];
    const float* Wkv  = (const float*)d_in[3];
    const float* Wlin = (const float*)d_in[4];
    const float* blin = (const float*)d_in[5];
    float* out        = (float*)d_out;

    void *pqkv, *pxs, *pctxs, *pwqkv, *pwlins;
    cudaGetSymbolAddress(&pqkv, g_qkv);
    cudaGetSymbolAddress(&pxs, g_xs);
    cudaGetSymbolAddress(&pctxs, g_ctxs);
    cudaGetSymbolAddress(&pwqkv, g_wqkv);
    cudaGetSymbolAddress(&pwlins, g_wlins);
    float* qkv = (float*)pqkv;
    __nv_bfloat16* xs    = (__nv_bfloat16*)pxs;
    __nv_bfloat16* ctxs  = (__nv_bfloat16*)pctxs;
    __nv_bfloat16* wqkv  = (__nv_bfloat16*)pwqkv;
    __nv_bfloat16* wlins = (__nv_bfloat16*)pwlins;

    const int gemm_smem = NSTG * STGB;   // 61440
    cudaFuncSetAttribute(gemm_mma, cudaFuncAttributeMaxDynamicSharedMemorySize, gemm_smem);
    cudaFuncSetAttribute(attn_mma, cudaFuncAttributeMaxDynamicSharedMemorySize, AT_SMEM);

    // one fused split for all pre-GEMM conversions
    {
        const int total = NX + NQ + NKV2 + NL;
        split_all<<<(total + 255) / 256, 256>>>(x, Wq, Wkv, Wlin, xs, wqkv, wlins);
    }

    // fused Q+KV projection: 4096 x 1536
    {
        dim3 grid(1536 / 128, NTOK / 128);
        gemm_mma<<<grid, 256, gemm_smem>>>(xs, wqkv, qkv, 1536, nullptr);
    }
    // RoPE on q and k_p sections
    rope_kernel<<<NTOK, 256>>>(qkv);

    // MMA attention (writes split-bf16 ctx directly)
    {
        dim3 grid(TT / 64, HH, BB);
        attn_mma<<<grid, 128, AT_SMEM>>>(qkv, mk, ctxs);
    }

    // output projection + bias
    {
        dim3 grid(DM / 128, NTOK / 128);
        gemm_mma<<<grid, 256, gemm_smem>>>(ctxs, wlins, out, DM, blin);
    }
}

// round 10
// speedup vs baseline: 2.2446x; 1.0766x over previous
#include <cuda_runtime.h>
#include <cuda_bf16.h>
#include <cstdint>

// Problem constants
#define BB 2
#define TT 2048
#define QDIM 512
#define HH 8
#define DHH 64
#define WW 64
#define DM 512
#define NTOK (BB*TT)

// Split-bf16 GEMM constants: K' = 3*512 (hi|hi|lo vs hi|lo|hi)
#define GK 1536
#define KT 32
#define NKT (GK/KT)
#define ROWB 80
#define ASTG (128*ROWB)
#define STGB (2*ASTG)
#define NSTG 3

// Scratch (static device globals; no allocs allowed)
__device__ float g_qkv[(size_t)NTOK * 1536];
__device__ __nv_bfloat16 g_att[(size_t)NTOK * 3072];   // [qhi|qlo|chi|clo]
__device__ __nv_bfloat16 g_xs[(size_t)NTOK * GK];
__device__ __nv_bfloat16 g_ctxs[(size_t)NTOK * GK];
__device__ __nv_bfloat16 g_wqkv[(size_t)1536 * GK];
__device__ __nv_bfloat16 g_wlins[(size_t)DM * GK];

__device__ __forceinline__ uint32_t smem_u32(const void* p) {
    uint32_t a;
    asm("{ .reg .u64 t; cvta.to.shared.u64 t, %1; cvt.u32.u64 %0, t; }" : "=r"(a) : "l"(p));
    return a;
}

// pack two f32 into bf16x2 (first arg -> low half = first element in memory)
__device__ __forceinline__ uint32_t packbf2(float lo, float hi) {
    uint32_t d;
    asm("cvt.rn.bf16x2.f32 %0, %1, %2;" : "=r"(d) : "f"(hi), "f"(lo));
    return d;
}

__device__ __forceinline__ void ldsm4(uint32_t r[4], uint32_t addr) {
    asm volatile("ldmatrix.sync.aligned.m8n8.x4.shared.b16 {%0,%1,%2,%3}, [%4];"
                 : "=r"(r[0]), "=r"(r[1]), "=r"(r[2]), "=r"(r[3]) : "r"(addr));
}
__device__ __forceinline__ void ldsm4t(uint32_t r[4], uint32_t addr) {
    asm volatile("ldmatrix.sync.aligned.m8n8.x4.trans.shared.b16 {%0,%1,%2,%3}, [%4];"
                 : "=r"(r[0]), "=r"(r[1]), "=r"(r[2]), "=r"(r[3]) : "r"(addr));
}
__device__ __forceinline__ void mma16816(float c[4], const uint32_t a[4],
                                         uint32_t b0, uint32_t b1) {
    asm volatile(
        "mma.sync.aligned.m16n8k16.row.col.f32.bf16.bf16.f32 "
        "{%0,%1,%2,%3}, {%4,%5,%6,%7}, {%8,%9}, {%0,%1,%2,%3};"
        : "+f"(c[0]), "+f"(c[1]), "+f"(c[2]), "+f"(c[3])
        : "r"(a[0]), "r"(a[1]), "r"(a[2]), "r"(a[3]), "r"(b0), "r"(b1));
}
// cp.async with zfill when !ok (src-size 0 -> zero fill)
__device__ __forceinline__ void cp16(uint32_t dst, const void* src, bool ok) {
    const int sz = ok ? 16 : 0;
    asm volatile("cp.async.cg.shared.global [%0], [%1], 16, %2;"
                 :: "r"(dst), "l"(src), "r"(sz) : "memory");
}

// ---------------------------------------------------------------------------
// Fused split kernel (pre-GEMM conversions, one launch).
// A pattern: [hi | hi | lo].  B pattern: [hi | lo | hi].
// ---------------------------------------------------------------------------
#define NX (NTOK*512)
#define NQ (512*512)
#define NKV2 (1024*512)
#define NL (512*512)

__global__ void split_all(const float* __restrict__ x,
                          const float* __restrict__ Wq,
                          const float* __restrict__ Wkv,
                          const float* __restrict__ Wlin,
                          __nv_bfloat16* __restrict__ xs,
                          __nv_bfloat16* __restrict__ wqkv,
                          __nv_bfloat16* __restrict__ wlins)
{
    const int i = blockIdx.x * blockDim.x + threadIdx.x;
    float a;
    __nv_bfloat16* out;
    int r, c, bpat;
    if (i < NX) {
        a = x[i]; r = i >> 9; c = i & 511; out = xs; bpat = 0;
    } else if (i < NX + NQ) {
        const int j = i - NX;
        a = Wq[j]; r = j >> 9; c = j & 511; out = wqkv; bpat = 1;
    } else if (i < NX + NQ + NKV2) {
        const int j = i - NX - NQ;
        a = Wkv[j]; r = 512 + (j >> 9); c = j & 511; out = wqkv; bpat = 1;
    } else if (i < NX + NQ + NKV2 + NL) {
        const int j = i - NX - NQ - NKV2;
        a = Wlin[j]; r = j >> 9; c = j & 511; out = wlins; bpat = 1;
    } else return;

    const __nv_bfloat16 h = __float2bfloat16_rn(a);
    const __nv_bfloat16 l = __float2bfloat16_rn(a - __bfloat162float(h));
    const size_t base = (size_t)r * GK + c;
    out[base] = h;
    if (bpat) { out[base + 512] = l; out[base + 1024] = h; }
    else      { out[base + 512] = h; out[base + 1024] = l; }
}

// ---------------------------------------------------------------------------
// mma.sync bf16 GEMM: C = A'.B'^T (+bias), fp32 accum.
// Block 128x128, 256 threads, 3-stage cp.async pipeline.
// ---------------------------------------------------------------------------
__global__ __launch_bounds__(256, 2) void gemm_mma(
    const __nv_bfloat16* __restrict__ A,
    const __nv_bfloat16* __restrict__ B,
    float* __restrict__ C, int Ntot,
    const float* __restrict__ bias)
{
    extern __shared__ char smem[];
    const uint32_t sbase = smem_u32(smem);

    const int tid  = threadIdx.x;
    const int lane = tid & 31;
    const int warp = tid >> 5;
    const int wm   = warp & 3;
    const int wn   = warp >> 2;
    const int m0   = blockIdx.y * 128;
    const int n0   = blockIdx.x * 128;

    const int ldRow = tid >> 2;
    const int ldJ   = tid & 3;
    const __nv_bfloat16* gA0 = A + (size_t)(m0 + ldRow) * GK + ldJ * 8;
    const __nv_bfloat16* gA1 = A + (size_t)(m0 + ldRow + 64) * GK + ldJ * 8;
    const __nv_bfloat16* gB0 = B + (size_t)(n0 + ldRow) * GK + ldJ * 8;
    const __nv_bfloat16* gB1 = B + (size_t)(n0 + ldRow + 64) * GK + ldJ * 8;
    const uint32_t sRow0 = ldRow * ROWB + ldJ * 16;
    const uint32_t sRow1 = (ldRow + 64) * ROWB + ldJ * 16;

    float c[2][8][4];
#pragma unroll
    for (int i = 0; i < 2; i++)
#pragma unroll
        for (int j = 0; j < 8; j++)
#pragma unroll
            for (int k = 0; k < 4; k++) c[i][j][k] = 0.f;

    auto issue = [&](int stage, int kt) {
        const uint32_t sa = sbase + stage * STGB;
        const uint32_t sb = sa + ASTG;
        const size_t ko = (size_t)kt * KT;
        asm volatile("cp.async.cg.shared.global [%0], [%1], 16;"
                     :: "r"(sa + sRow0), "l"(gA0 + ko) : "memory");
        asm volatile("cp.async.cg.shared.global [%0], [%1], 16;"
                     :: "r"(sa + sRow1), "l"(gA1 + ko) : "memory");
        asm volatile("cp.async.cg.shared.global [%0], [%1], 16;"
                     :: "r"(sb + sRow0), "l"(gB0 + ko) : "memory");
        asm volatile("cp.async.cg.shared.global [%0], [%1], 16;"
                     :: "r"(sb + sRow1), "l"(gB1 + ko) : "memory");
        asm volatile("cp.async.commit_group;" ::: "memory");
    };

    issue(0, 0);
    issue(1, 1);

    const uint32_t aRowOff = (uint32_t)(wm * 32 + (lane & 15)) * ROWB
                           + ((lane >> 4) << 4);
    const uint32_t bRowOff = (uint32_t)(wn * 64 + (lane & 7) + ((lane & 16) >> 1)) * ROWB
                           + ((lane & 8) << 1);

    for (int kt = 0; kt < NKT; kt++) {
        if (kt < NKT - 2) asm volatile("cp.async.wait_group 1;" ::: "memory");
        else              asm volatile("cp.async.wait_group 0;" ::: "memory");
        __syncthreads();

        const int stage = kt % NSTG;
        const uint32_t sa = sbase + stage * STGB;
        const uint32_t sb = sa + ASTG;

#pragma unroll
        for (int ks = 0; ks < 2; ks++) {
            uint32_t a[2][4];
#pragma unroll
            for (int mt = 0; mt < 2; mt++)
                ldsm4(a[mt], sa + aRowOff + mt * 16 * ROWB + ks * 32);
            uint32_t b[4][4];
#pragma unroll
            for (int p = 0; p < 4; p++)
                ldsm4(b[p], sb + bRowOff + p * 16 * ROWB + ks * 32);
#pragma unroll
            for (int mt = 0; mt < 2; mt++)
#pragma unroll
                for (int nt = 0; nt < 8; nt++) {
                    const int p = nt >> 1, q = (nt & 1) * 2;
                    mma16816(c[mt][nt], a[mt], b[p][q], b[p][q + 1]);
                }
        }

        if (kt + 2 < NKT) issue((kt + 2) % NSTG, kt + 2);
    }

#pragma unroll
    for (int mt = 0; mt < 2; mt++) {
        const int gm = m0 + wm * 32 + mt * 16 + (lane >> 2);
#pragma unroll
        for (int nt = 0; nt < 8; nt++) {
            const int gn = n0 + wn * 64 + nt * 8 + (lane & 3) * 2;
            float2 v0 = make_float2(c[mt][nt][0], c[mt][nt][1]);
            float2 v1 = make_float2(c[mt][nt][2], c[mt][nt][3]);
            if (bias) {
                const float b0 = bias[gn], b1 = bias[gn + 1];
                v0.x += b0; v0.y += b1;
                v1.x += b0; v1.y += b1;
            }
            *(float2*)&C[(size_t)gm * Ntot + gn]       = v0;
            *(float2*)&C[(size_t)(gm + 8) * Ntot + gn] = v1;
        }
    }
}

// ---------------------------------------------------------------------------
// RoPE + split to bf16 planes. Input: qkv fp32 row [q|k_p|v_p] (1536).
// Output att row (3072 bf16): [qhi(512) | qlo(512) | chi(1024) | clo(1024)],
// where c = [rope(k_p) | v_p]. Threads 0..127: q and k pairs (cols 2j, 2j+1
// with partners +256). Threads 128..255: v (4 cols each).
// ---------------------------------------------------------------------------
__global__ void rope_split(const float* __restrict__ qkv,
                           __nv_bfloat16* __restrict__ att)
{
    const int row = blockIdx.x;
    const int tid = threadIdx.x;
    const int t = row & (TT - 1);
    const float* pr = qkv + (size_t)row * 1536;
    __nv_bfloat16* po = att + (size_t)row * 3072;

    if (tid < 128) {
        float qy1[2], qy2[2], ky1[2], ky2[2];
#pragma unroll
        for (int e = 0; e < 2; e++) {
            const int c = 2 * tid + e;
            const float inv = powf(100.0f, -(float)c * (1.0f / 256.0f));
            const float ang = (float)t * inv;
            float s, co;
            sincosf(ang, &s, &co);
            float x1 = pr[c], x2 = pr[c + 256];
            qy1[e] = x1 * co - x2 * s;
            qy2[e] = x2 * co + x1 * s;
            x1 = pr[512 + c]; x2 = pr[512 + c + 256];
            ky1[e] = x1 * co - x2 * s;
            ky2[e] = x2 * co + x1 * s;
        }
        const int c0 = 2 * tid;
        {
            const float h0 = __bfloat162float(__float2bfloat16_rn(qy1[0]));
            const float h1 = __bfloat162float(__float2bfloat16_rn(qy1[1]));
            const float g0 = __bfloat162float(__float2bfloat16_rn(qy2[0]));
            const float g1 = __bfloat162float(__float2bfloat16_rn(qy2[1]));
            *(uint32_t*)(po + c0)             = packbf2(qy1[0], qy1[1]);
            *(uint32_t*)(po + c0 + 256)       = packbf2(qy2[0], qy2[1]);
            *(uint32_t*)(po + 512 + c0)       = packbf2(qy1[0] - h0, qy1[1] - h1);
            *(uint32_t*)(po + 512 + c0 + 256) = packbf2(qy2[0] - g0, qy2[1] - g1);
        }
        {
            const float h0 = __bfloat162float(__float2bfloat16_rn(ky1[0]));
            const float h1 = __bfloat162float(__float2bfloat16_rn(ky1[1]));
            const float g0 = __bfloat162float(__float2bfloat16_rn(ky2[0]));
            const float g1 = __bfloat162float(__float2bfloat16_rn(ky2[1]));
            *(uint32_t*)(po + 1024 + c0)       = packbf2(ky1[0], ky1[1]);
            *(uint32_t*)(po + 1024 + c0 + 256) = packbf2(ky2[0], ky2[1]);
            *(uint32_t*)(po + 2048 + c0)       = packbf2(ky1[0] - h0, ky1[1] - h1);
            *(uint32_t*)(po + 2048 + c0 + 256) = packbf2(ky2[0] - g0, ky2[1] - g1);
        }
    } else {
        const int c = 4 * (tid - 128);
        const float4 v = *(const float4*)(pr + 1024 + c);
        const float hx = __bfloat162float(__float2bfloat16_rn(v.x));
        const float hy = __bfloat162float(__float2bfloat16_rn(v.y));
        const float hz = __bfloat162float(__float2bfloat16_rn(v.z));
        const float hw = __bfloat162float(__float2bfloat16_rn(v.w));
        *(uint2*)(po + 1536 + c) = make_uint2(packbf2(v.x, v.y), packbf2(v.z, v.w));
        *(uint2*)(po + 2560 + c) = make_uint2(packbf2(v.x - hx, v.y - hy),
                                              packbf2(v.z - hz, v.w - hw));
    }
}

// ---------------------------------------------------------------------------
// MMA sliding-window sigmoid attention (band-restricted, pre-split operands).
// Per block: (b, h, 64 q rows), 128 threads (4 warps). Warp w: q rows
// [16w,16w+16), keys local r in [16w, 16w+80) (band w = r - qi in [0,64)).
// K tile rows r=0..127 map to t = t0-63+r. att row layout: qhi@0 qlo@512
// chi@1024 clo@2048; head h: K = c[128h:128h+64], V = c[128h+64:128h+128].
// ---------------------------------------------------------------------------
#define AT_ROWB 144
#define SM_QHI 0
#define SM_QLO 9216
#define SM_KHI 18432
#define SM_KLO 36864
#define SM_VHI 55296
#define SM_VLO 73728
#define AT_SMEM 92160

__global__ __launch_bounds__(128, 2) void attn_mma(
    const __nv_bfloat16* __restrict__ att,
    const int* __restrict__ mask,
    __nv_bfloat16* __restrict__ ctxs)
{
    extern __shared__ char smem[];
    const uint32_t sb = smem_u32(smem);

    const int t0 = blockIdx.x * 64;
    const int h  = blockIdx.y;
    const int b  = blockIdx.z;
    const int tid  = threadIdx.x;
    const int lane = tid & 31;
    const int warp = tid >> 5;

    const __nv_bfloat16* gatt = att + (size_t)b * TT * 3072;

    // ---- cp.async prologue ----
    // Q hi/lo: 64 rows x 2 bufs x 8 chunks = 1024 x 16B
    for (int i = tid; i < 1024; i += 128) {
        const int r = i >> 4, rem = i & 15;
        const int buf = rem >> 3, ch = rem & 7;
        const __nv_bfloat16* src = gatt + (size_t)(t0 + r) * 3072
                                 + buf * 512 + h * 64 + ch * 8;
        const uint32_t dst = sb + (buf ? SM_QLO : SM_QHI) + r * AT_ROWB + ch * 16;
        cp16(dst, src, true);
    }
    // K/V hi/lo: 128 rows x {K,V} x {hi,lo} x 8 chunks = 4096 x 16B
    for (int i = tid; i < 4096; i += 128) {
        const int r = i >> 5, rem = i & 31;
        const int kv = rem >> 4, buf = (rem >> 3) & 1, ch = rem & 7;
        const int tk = t0 - 63 + r;
        const bool ok = (tk >= 0 && tk < TT);
        const int col = (buf ? 2048 : 1024) + h * 128 + kv * 64 + ch * 8;
        const __nv_bfloat16* src = gatt + (size_t)(ok ? tk : 0) * 3072 + col;
        const uint32_t base = kv ? (buf ? SM_VLO : SM_VHI) : (buf ? SM_KLO : SM_KHI);
        const uint32_t dst = sb + base + r * AT_ROWB + ch * 16;
        cp16(dst, src, ok);
    }
    asm volatile("cp.async.commit_group;" ::: "memory");
    asm volatile("cp.async.wait_group 0;" ::: "memory");
    __syncthreads();

    // ---- QK^T: warp tile m16 x n80 (keys r in [m0, m0+80)), 3-term split ----
    const int m0 = warp * 16;
    const uint32_t aOff = (uint32_t)(m0 + (lane & 15)) * AT_ROWB + ((lane >> 4) << 4);
    const uint32_t bOff = (uint32_t)(m0 + (lane & 7) + ((lane & 16) >> 1)) * AT_ROWB
                        + ((lane & 8) << 1);

    float cs[10][4];
#pragma unroll
    for (int i = 0; i < 10; i++)
#pragma unroll
        for (int j = 0; j < 4; j++) cs[i][j] = 0.f;

#pragma unroll
    for (int ks = 0; ks < 4; ks++) {
        uint32_t ah[4], al[4];
        ldsm4(ah, sb + SM_QHI + aOff + ks * 32);
        ldsm4(al, sb + SM_QLO + aOff + ks * 32);
#pragma unroll
        for (int ng = 0; ng < 5; ng++) {
            uint32_t bh[4], bl[4];
            ldsm4(bh, sb + SM_KHI + ng * (16 * AT_ROWB) + ks * 32 + bOff);
            mma16816(cs[2 * ng],     ah, bh[0], bh[1]);
            mma16816(cs[2 * ng + 1], ah, bh[2], bh[3]);
            mma16816(cs[2 * ng],     al, bh[0], bh[1]);
            mma16816(cs[2 * ng + 1], al, bh[2], bh[3]);
            ldsm4(bl, sb + SM_KLO + ng * (16 * AT_ROWB) + ks * 32 + bOff);
            mma16816(cs[2 * ng],     ah, bl[0], bl[1]);
            mma16816(cs[2 * ng + 1], ah, bl[2], bl[3]);
        }
    }

    // ---- sigmoid + band + mask in registers; split S to bf16 hi/lo ----
    const float SCALE = 0.125f;
    const float LOGW  = 4.1588830833596718f;
    const int qa = m0 + (lane >> 2);
    const int qb = qa + 8;
    const bool mka = mask[(size_t)b * TT + t0 + qa] != 0;
    const bool mkb = mask[(size_t)b * TT + t0 + qb] != 0;

    uint32_t SH[10][2], SL[10][2];
#pragma unroll
    for (int nt = 0; nt < 10; nt++) {
        const int r0 = m0 + nt * 8 + (lane & 3) * 2;    // absolute key row
        float s[4];
#pragma unroll
        for (int e = 0; e < 2; e++) {
            const int r = r0 + e;
            {
                const int w = r - qa;
                float v = 0.f;
                if (w >= 0 && w < 64 && mka) {
                    const float val = cs[nt][e] * SCALE - LOGW;
                    v = 1.f / (1.f + __expf(-val));
                }
                s[e] = v;
            }
            {
                const int w = r - qb;
                float v = 0.f;
                if (w >= 0 && w < 64 && mkb) {
                    const float val = cs[nt][2 + e] * SCALE - LOGW;
                    v = 1.f / (1.f + __expf(-val));
                }
                s[2 + e] = v;
            }
        }
        const float h0 = __bfloat162float(__float2bfloat16_rn(s[0]));
        const float h1 = __bfloat162float(__float2bfloat16_rn(s[1]));
        const float h2 = __bfloat162float(__float2bfloat16_rn(s[2]));
        const float h3 = __bfloat162float(__float2bfloat16_rn(s[3]));
        SH[nt][0] = packbf2(s[0], s[1]);
        SH[nt][1] = packbf2(s[2], s[3]);
        SL[nt][0] = packbf2(s[0] - h0, s[1] - h1);
        SL[nt][1] = packbf2(s[2] - h2, s[3] - h3);
    }

    // ---- PV: C(16x64) = S(16x80) x V(80x64), V rows [m0, m0+80) ----
    float co[8][4];
#pragma unroll
    for (int i = 0; i < 8; i++)
#pragma unroll
        for (int j = 0; j < 4; j++) co[i][j] = 0.f;

    const uint32_t vOff = (uint32_t)((lane & 7) + (lane & 8)) * AT_ROWB
                        + ((lane & 16) >> 4) * 16;

#pragma unroll
    for (int ks = 0; ks < 5; ks++) {
        const uint32_t aH[4] = { SH[2*ks][0], SH[2*ks][1], SH[2*ks+1][0], SH[2*ks+1][1] };
        const uint32_t aL[4] = { SL[2*ks][0], SL[2*ks][1], SL[2*ks+1][0], SL[2*ks+1][1] };
        const uint32_t kOff = (uint32_t)(m0 + ks * 16) * AT_ROWB + vOff;
#pragma unroll
        for (int ng = 0; ng < 4; ng++) {
            uint32_t vh[4], vl[4];
            ldsm4t(vh, sb + SM_VHI + kOff + ng * 32);
            mma16816(co[2 * ng],     aH, vh[0], vh[1]);
            mma16816(co[2 * ng + 1], aH, vh[2], vh[3]);
            mma16816(co[2 * ng],     aL, vh[0], vh[1]);
            mma16816(co[2 * ng + 1], aL, vh[2], vh[3]);
            ldsm4t(vl, sb + SM_VLO + kOff + ng * 32);
            mma16816(co[2 * ng],     aH, vl[0], vl[1]);
            mma16816(co[2 * ng + 1], aH, vl[2], vl[3]);
        }
    }

    // ---- epilogue: write split-bf16 ctx (A pattern: hi, hi, lo) ----
    const size_t rowA = (size_t)(b * TT + t0 + qa) * GK + h * DHH;
    const size_t rowB = (size_t)(b * TT + t0 + qb) * GK + h * DHH;
#pragma unroll
    for (int nt = 0; nt < 8; nt++) {
        const int d = nt * 8 + (lane & 3) * 2;
        const float h0 = __bfloat162float(__float2bfloat16_rn(co[nt][0]));
        const float h1 = __bfloat162float(__float2bfloat16_rn(co[nt][1]));
        const float h2 = __bfloat162float(__float2bfloat16_rn(co[nt][2]));
        const float h3 = __bfloat162float(__float2bfloat16_rn(co[nt][3]));
        const uint32_t hA = packbf2(co[nt][0], co[nt][1]);
        const uint32_t lA = packbf2(co[nt][0] - h0, co[nt][1] - h1);
        const uint32_t hB = packbf2(co[nt][2], co[nt][3]);
        const uint32_t lB = packbf2(co[nt][2] - h2, co[nt][3] - h3);
        *(uint32_t*)(ctxs + rowA + d)        = hA;
        *(uint32_t*)(ctxs + rowA + 512 + d)  = hA;
        *(uint32_t*)(ctxs + rowA + 1024 + d) = lA;
        *(uint32_t*)(ctxs + rowB + d)        = hB;
        *(uint32_t*)(ctxs + rowB + 512 + d)  = hB;
        *(uint32_t*)(ctxs + rowB + 1024 + d) = lB;
    }
}

// ---------------------------------------------------------------------------
// Launch
// ---------------------------------------------------------------------------
extern "C" void kernel_launch(void* const* d_in, const int* in_sizes, int n_in,
                              void* d_out, int out_size)
{
    const float* x    = (const float*)d_in[0];
    const int* mk     = (const int*)d_in[1];     // bool delivered as int32
    const float* Wq   = (const float*)d_in[2];
    const float* Wkv  = (const float*)d_in[3];
    const float* Wlin = (const float*)d_in[4];
    const float* blin = (const float*)d_in[5];
    float* out        = (float*)d_out;

    void *pqkv, *patt, *pxs, *pctxs, *pwqkv, *pwlins;
    cudaGetSymbolAddress(&pqkv, g_qkv);
    cudaGetSymbolAddress(&patt, g_att);
    cudaGetSymbolAddress(&pxs, g_xs);
    cudaGetSymbolAddress(&pctxs, g_ctxs);
    cudaGetSymbolAddress(&pwqkv, g_wqkv);
    cudaGetSymbolAddress(&pwlins, g_wlins);
    float* qkv = (float*)pqkv;
    __nv_bfloat16* att   = (__nv_bfloat16*)patt;
    __nv_bfloat16* xs    = (__nv_bfloat16*)pxs;
    __nv_bfloat16* ctxs  = (__nv_bfloat16*)pctxs;
    __nv_bfloat16* wqkv  = (__nv_bfloat16*)pwqkv;
    __nv_bfloat16* wlins = (__nv_bfloat16*)pwlins;

    const int gemm_smem = NSTG * STGB;
    cudaFuncSetAttribute(gemm_mma, cudaFuncAttributeMaxDynamicSharedMemorySize, gemm_smem);
    cudaFuncSetAttribute(attn_mma, cudaFuncAttributeMaxDynamicSharedMemorySize, AT_SMEM);

    // one fused split for all pre-GEMM conversions
    {
        const int total = NX + NQ + NKV2 + NL;
        split_all<<<(total + 255) / 256, 256>>>(x, Wq, Wkv, Wlin, xs, wqkv, wlins);
    }

    // fused Q+KV projection: 4096 x 1536
    {
        dim3 grid(1536 / 128, NTOK / 128);
        gemm_mma<<<grid, 256, gemm_smem>>>(xs, wqkv, qkv, 1536, nullptr);
    }
    // RoPE + split to bf16 planes
    rope_split<<<NTOK, 256>>>(qkv, att);

    // MMA attention (band-restricted, pre-split operands)
    {
        dim3 grid(TT / 64, HH, BB);
        attn_mma<<<grid, 128, AT_SMEM>>>(att, mk, ctxs);
    }

    // output projection + bias
    {
        dim3 grid(DM / 128, NTOK / 128);
        gemm_mma<<<grid, 256, gemm_smem>>>(ctxs, wlins, out, DM, blin);
    }
}